// round 13
// baseline (speedup 1.0000x reference)
#include <cuda_runtime.h>
#include <cuda_bf16.h>
#include <limits.h>

// Single self-sufficient kernel: block `seg` finds first/last occurrence of
// its own segment id by scanning the L2-resident mask (broadcast across
// blocks), then copies the two rows. No global scratch, no global atomics,
// trivially graph-replay-safe.
//
// Scan: forward + backward windows in the same round, all loads issued
// unconditionally (8 independent LDGs/thread, no chains). Row data moves
// with streaming hints (__ldcs/__stcs): rows are touched exactly once, so
// L2 stays reserved for the 512x-reused mask.

#define NTHR 256
#define WIN  1024            // ids per window per direction (4 per thread)
#define KPT  (WIN / NTHR)    // 4

__global__ void __launch_bounds__(NTHR) fused_gather_kernel(
        const float* __restrict__ x,
        const int*   __restrict__ mask,
        float*       __restrict__ out,
        int L, int H) {
    const int seg = blockIdx.x;
    const int tid = threadIdx.x;

    __shared__ int s_first, s_last;
    if (tid == 0) { s_first = INT_MAX; s_last = -1; }

    int first = INT_MAX, last = -1;
    int fbase = 0;           // forward window base
    int bend  = L;           // backward window end (exclusive)

    for (;;) {
        // ---- batched, unconditional loads for both windows ----
        int fidx[KPT], fval[KPT], bidx[KPT], bval[KPT];
        bool doF = (first == INT_MAX) && (fbase < L);
        bool doB = (last < 0) && (bend > 0);
        int bstart = bend - WIN > 0 ? bend - WIN : 0;
        #pragma unroll
        for (int k = 0; k < KPT; k++) {
            fidx[k] = fbase + tid + k * NTHR;
            bidx[k] = bstart + tid + k * NTHR;
            fval[k] = (doF && fidx[k] < L)    ? __ldg(mask + fidx[k]) : -1;
            bval[k] = (doB && bidx[k] < bend) ? __ldg(mask + bidx[k]) : -1;
        }
        // ---- local reduce, then block reduce via shared atomics ----
        int lf = INT_MAX, lb = -1;
        #pragma unroll
        for (int k = 0; k < KPT; k++) {
            if (fval[k] == seg && fidx[k] < lf) lf = fidx[k];
            if (bval[k] == seg && bidx[k] > lb) lb = bidx[k];
        }
        if (lf != INT_MAX) atomicMin(&s_first, lf);
        if (lb >= 0)       atomicMax(&s_last, lb);
        __syncthreads();
        first = s_first;
        last  = s_last;
        if (first != INT_MAX && last >= 0) break;        // hit path: 1 barrier
        fbase += WIN;
        bend  = bstart;
        if (fbase >= L && bend <= 0) break;              // segment absent
        __syncthreads();     // protect s_first/s_last reuse next round
    }

    if (first == INT_MAX || last < 0) return;            // segment absent

    // ---- copy first/last rows (streaming both ways; 1 iter for H=1024) ----
    const float4* __restrict__ f4 = (const float4*)(x + (size_t)first * H);
    const float4* __restrict__ l4 = (const float4*)(x + (size_t)last  * H);
    float4* __restrict__ o4 = (float4*)(out + (size_t)seg * (2 * H));

    int nvec = H / 4;
    for (int t = tid; t < nvec; t += NTHR) {
        float4 a = __ldcs(f4 + t);   // evict-first: row read exactly once
        float4 b = __ldcs(l4 + t);
        __stcs(o4 + t,        a);    // streaming store: out is write-once
        __stcs(o4 + nvec + t, b);
    }
}

extern "C" void kernel_launch(void* const* d_in, const int* in_sizes, int n_in,
                              void* d_out, int out_size) {
    const float* x    = (const float*)d_in[0];
    const int*   mask = (const int*)d_in[1];
    float*       out  = (float*)d_out;

    int L = in_sizes[1];          // B*S = 32768
    int H = in_sizes[0] / L;      // 1024
    int n = out_size / (2 * H);   // 512

    fused_gather_kernel<<<n, NTHR>>>(x, mask, out, L, H);
}

// round 14
// speedup vs baseline: 1.3462x; 1.3462x over previous
#include <cuda_runtime.h>
#include <cuda_bf16.h>
#include <limits.h>

// Single self-sufficient kernel: block `seg` finds first/last occurrence of
// its own segment id by scanning the L2-resident mask (broadcast across
// blocks), then copies the two rows. No global scratch, no global atomics,
// trivially graph-replay-safe.
//
// Scan: forward + backward windows processed in the SAME round with all
// window loads issued unconditionally (8 independent LDGs in flight per
// thread) — no load chains, 2 barriers per round. For the bench input both
// hits land in round 0; the loop keeps it correct for arbitrary masks.
//
// Measured design points (GB300, this bench):
//   - 256 thr/block beats 512 (512 adds ramp+ALU, copy is not issue-bound)
//   - __ldg row loads beat __ldcs (evict-first loses coalescing; L2 is not
//     under pressure at 8.4 MB working set)
//   - __stcs stores help (write-once output)
//   - fused-with-window-scan beats 2-kernel, PDL, and grid-barrier variants

#define NTHR 256
#define WIN  1024            // ids per window (4 per thread)
#define KPT  (WIN / NTHR)    // 4

__global__ void __launch_bounds__(NTHR) fused_gather_kernel(
        const float* __restrict__ x,
        const int*   __restrict__ mask,
        float*       __restrict__ out,
        int L, int H) {
    const int seg = blockIdx.x;
    const int tid = threadIdx.x;

    __shared__ int s_first, s_last;
    if (tid == 0) { s_first = INT_MAX; s_last = -1; }

    int first = INT_MAX, last = -1;
    int fbase = 0;           // forward window base
    int bend  = L;           // backward window end (exclusive)

    while (first == INT_MAX || last < 0) {
        // ---- batched, unconditional loads for both windows ----
        int fidx[KPT], fval[KPT], bidx[KPT], bval[KPT];
        bool doF = (first == INT_MAX) && (fbase < L);
        bool doB = (last < 0) && (bend > 0);
        int bstart = bend - WIN > 0 ? bend - WIN : 0;
        #pragma unroll
        for (int k = 0; k < KPT; k++) {
            fidx[k] = fbase + tid + k * NTHR;
            bidx[k] = bstart + tid + k * NTHR;
            fval[k] = (doF && fidx[k] < L)    ? __ldg(mask + fidx[k]) : -1;
            bval[k] = (doB && bidx[k] < bend) ? __ldg(mask + bidx[k]) : -1;
        }
        // ---- local reduce ----
        int lf = INT_MAX, lb = -1;
        #pragma unroll
        for (int k = 0; k < KPT; k++) {
            if (fval[k] == seg && fidx[k] < lf) lf = fidx[k];
            if (bval[k] == seg && bidx[k] > lb) lb = bidx[k];
        }
        if (lf != INT_MAX) atomicMin(&s_first, lf);
        if (lb >= 0)       atomicMax(&s_last, lb);
        __syncthreads();
        first = s_first;
        last  = s_last;
        fbase += WIN;
        bend  = bstart;
        if ((first == INT_MAX && fbase >= L) && (last < 0 && bend <= 0)) break;
        __syncthreads();     // protect s_first/s_last reuse next round
    }

    if (first == INT_MAX || last < 0) return;   // segment absent

    // ---- copy first/last rows (float4; H=1024 -> 1 iter/thread) ----
    const float4* __restrict__ f4 = (const float4*)(x + (size_t)first * H);
    const float4* __restrict__ l4 = (const float4*)(x + (size_t)last  * H);
    float4* __restrict__ o4 = (float4*)(out + (size_t)seg * (2 * H));

    int nvec = H / 4;
    for (int t = tid; t < nvec; t += NTHR) {
        float4 a = __ldg(f4 + t);
        float4 b = __ldg(l4 + t);
        __stcs(o4 + t,        a);   // streaming store: out is write-once
        __stcs(o4 + nvec + t, b);
    }
}

extern "C" void kernel_launch(void* const* d_in, const int* in_sizes, int n_in,
                              void* d_out, int out_size) {
    const float* x    = (const float*)d_in[0];
    const int*   mask = (const int*)d_in[1];
    float*       out  = (float*)d_out;

    int L = in_sizes[1];          // B*S = 32768
    int H = in_sizes[0] / L;      // 1024
    int n = out_size / (2 * H);   // 512

    fused_gather_kernel<<<n, NTHR>>>(x, mask, out, L, H);
}

// round 15
// speedup vs baseline: 1.3527x; 1.0048x over previous
#include <cuda_runtime.h>
#include <cuda_bf16.h>
#include <limits.h>

// Single self-sufficient kernel: block `seg` finds first/last occurrence of
// its own segment id by scanning the L2-resident mask (broadcast across
// blocks), then copies the two rows. No global scratch, no global atomics,
// trivially graph-replay-safe.
//
// Scan: forward + backward windows in one round. Each thread does ONE
// int4 load per direction (LDG.128), reduces candidates warp-locally via
// REDUX (__reduce_{min,max}_sync), then 1 shared atomic per warp.
//
// Measured design points (GB300, this bench):
//   - 256 thr/block beats 512; __ldg row loads beat __ldcs; __stcs stores
//     help; fused window-scan beats 2-kernel / PDL / grid-barrier.

#define NTHR 256
#define WIN  1024            // ids per window per direction (4 per thread)

__global__ void __launch_bounds__(NTHR) fused_gather_kernel(
        const float* __restrict__ x,
        const int*   __restrict__ mask,
        float*       __restrict__ out,
        int L, int H) {
    const int seg  = blockIdx.x;
    const int tid  = threadIdx.x;
    const int lane = tid & 31;

    __shared__ int s_first, s_last;
    if (tid == 0) { s_first = INT_MAX; s_last = -1; }

    int first = INT_MAX, last = -1;
    int fbase = 0;           // forward window base
    int bend  = L;           // backward window end (exclusive)

    while (first == INT_MAX || last < 0) {
        bool doF = (first == INT_MAX) && (fbase < L);
        bool doB = (last < 0) && (bend > 0);
        int bstart = bend - WIN > 0 ? bend - WIN : 0;

        // ---- one int4 load per direction per thread ----
        int fi0 = fbase + tid * 4;          // this thread's 4 fwd ids
        int bi0 = bstart + tid * 4;         // this thread's 4 bwd ids
        int4 fv = make_int4(-1, -1, -1, -1);
        int4 bv = make_int4(-1, -1, -1, -1);
        if (doF && fi0 + 3 < L)     fv = __ldg((const int4*)(mask + fi0));
        else if (doF) {                      // ragged tail (generality)
            if (fi0 + 0 < L) fv.x = __ldg(mask + fi0 + 0);
            if (fi0 + 1 < L) fv.y = __ldg(mask + fi0 + 1);
            if (fi0 + 2 < L) fv.z = __ldg(mask + fi0 + 2);
            if (fi0 + 3 < L) fv.w = __ldg(mask + fi0 + 3);
        }
        if (doB && bi0 + 3 < bend)  bv = __ldg((const int4*)(mask + bi0));
        else if (doB) {
            if (bi0 + 0 < bend) bv.x = __ldg(mask + bi0 + 0);
            if (bi0 + 1 < bend) bv.y = __ldg(mask + bi0 + 1);
            if (bi0 + 2 < bend) bv.z = __ldg(mask + bi0 + 2);
            if (bi0 + 3 < bend) bv.w = __ldg(mask + bi0 + 3);
        }

        // ---- local reduce (ids within a thread are ascending) ----
        int lf = INT_MAX, lb = -1;
        if (fv.x == seg) lf = fi0;          // first match = min
        else if (fv.y == seg) lf = fi0 + 1;
        else if (fv.z == seg) lf = fi0 + 2;
        else if (fv.w == seg) lf = fi0 + 3;
        if (bv.w == seg) lb = bi0 + 3;      // last match = max
        else if (bv.z == seg) lb = bi0 + 2;
        else if (bv.y == seg) lb = bi0 + 1;
        else if (bv.x == seg) lb = bi0;

        // ---- warp reduce (REDUX), then 1 shared atomic per warp ----
        int wf = __reduce_min_sync(0xffffffffu, lf);
        int wb = __reduce_max_sync(0xffffffffu, lb);
        if (lane == 0) {
            if (wf != INT_MAX) atomicMin(&s_first, wf);
            if (wb >= 0)       atomicMax(&s_last, wb);
        }
        __syncthreads();
        first = s_first;
        last  = s_last;
        fbase += WIN;
        bend  = bstart;
        if ((first == INT_MAX && fbase >= L) && (last < 0 && bend <= 0)) break;
        __syncthreads();     // protect s_first/s_last reuse next round
    }

    if (first == INT_MAX || last < 0) return;   // segment absent

    // ---- copy first/last rows (float4; H=1024 -> 1 iter/thread) ----
    const float4* __restrict__ f4 = (const float4*)(x + (size_t)first * H);
    const float4* __restrict__ l4 = (const float4*)(x + (size_t)last  * H);
    float4* __restrict__ o4 = (float4*)(out + (size_t)seg * (2 * H));

    int nvec = H / 4;
    for (int t = tid; t < nvec; t += NTHR) {
        float4 a = __ldg(f4 + t);
        float4 b = __ldg(l4 + t);
        __stcs(o4 + t,        a);   // streaming store: out is write-once
        __stcs(o4 + nvec + t, b);
    }
}

extern "C" void kernel_launch(void* const* d_in, const int* in_sizes, int n_in,
                              void* d_out, int out_size) {
    const float* x    = (const float*)d_in[0];
    const int*   mask = (const int*)d_in[1];
    float*       out  = (float*)d_out;

    int L = in_sizes[1];          // B*S = 32768
    int H = in_sizes[0] / L;      // 1024
    int n = out_size / (2 * H);   // 512

    fused_gather_kernel<<<n, NTHR>>>(x, mask, out, L, H);
}